// round 12
// baseline (speedup 1.0000x reference)
#include <cuda_runtime.h>
#include <cstdint>

// KANLinear fused as one tf32 mma.sync GEMM:
//   out[32768,256] = A[32768,2304] @ W[256,2304]^T
//   A = [ silu(x) | b_splines(x) flat ],  W = [ base_weight | spline_weight*scaler ]
// Round 10: CTA split to BM=128 x BN=128, TPB=256, __launch_bounds__(256,2) ->
// 2 independent CTAs per SM (barrier/latency hiding). W pre-fragmented in gmem
// (coalesced LDG.64, L2-resident); X staged through smem coalesced.
// 8 warps (2m x 4n), warp tile 64x32, K in 72 chunks of 32.

#define TPB 256
#define NCHUNK 72
// A layout: [mfrag 0..7][kstep 0..3][reg 0..3][lane 0..31], padded strides:
#define A_OFF(mf,ks,rg,ln) ((mf)*546 + (ks)*132 + (rg)*33 + (ln))
#define A_WORDS 4368          // 8*546
#define X_STRIDE 129          // k-major X stage: sX[k][row], padded row stride
#define X_WORDS (32 * X_STRIDE)
#define SMEM_BYTES ((2 * A_WORDS + 2 * X_WORDS) * 4)   // 67968

// W fragments: [chunk 0..71][nf_g 0..31][ks 0..3][lane 0..31] -> float2 (b0,b1)
__device__ float2 g_wfrag[NCHUNK * 32 * 4 * 32];

static __device__ __forceinline__ float tf32_rn(float f) {
    uint32_t u;
    asm("cvt.rna.tf32.f32 %0, %1;" : "=r"(u) : "f"(f));
    return __uint_as_float(u);
}

// ---------------- pre-kernel: build W fragments ----------------
static __device__ __forceinline__ float waug(
    int n, int K, const float* __restrict__ BW, const float* __restrict__ SW,
    const float* __restrict__ SS)
{
    if (K < 256) return tf32_rn(BW[(size_t)n * 256 + K]);
    int F = K - 256;
    int f = F >> 3, cf = F & 7;
    return tf32_rn(SW[((size_t)n * 256 + f) * 8 + cf] * SS[(size_t)n * 256 + f]);
}

__global__ void wfrag_kernel(const float* __restrict__ BW,
                             const float* __restrict__ SW,
                             const float* __restrict__ SS)
{
    int idx = blockIdx.x * 256 + threadIdx.x;          // 0 .. 294911
    int lane = idx & 31;
    int ks   = (idx >> 5) & 3;
    int nfg  = (idx >> 7) & 31;
    int c    = idx >> 12;
    int n = nfg * 8 + (lane >> 2);
    int t = lane & 3;
    int K0 = c * 32 + ks * 8 + t;
    float2 v;
    v.x = waug(n, K0,     BW, SW, SS);
    v.y = waug(n, K0 + 4, BW, SW, SS);
    g_wfrag[idx] = v;
}

// ---------------- main kernel helpers ----------------
static __device__ __forceinline__ void stage_x(
    int c, float* __restrict__ sX, int rbase, int tid, const float* __restrict__ X)
{
    if (c >= NCHUNK) return;
    if (c < 8) {
        // silu chunk: X[row][c*32 .. c*32+32); each 128B line read once
        const int row = tid & 127, half = tid >> 7;     // half in {0,1}: 16 k each
        const float4* p = reinterpret_cast<const float4*>(
            X + (size_t)(rbase + row) * 256 + c * 32 + half * 16);
        float4 a = p[0], b = p[1], d = p[2], e = p[3];
        const int k0 = half * 16;
        sX[(k0 +  0) * X_STRIDE + row] = a.x;
        sX[(k0 +  1) * X_STRIDE + row] = a.y;
        sX[(k0 +  2) * X_STRIDE + row] = a.z;
        sX[(k0 +  3) * X_STRIDE + row] = a.w;
        sX[(k0 +  4) * X_STRIDE + row] = b.x;
        sX[(k0 +  5) * X_STRIDE + row] = b.y;
        sX[(k0 +  6) * X_STRIDE + row] = b.z;
        sX[(k0 +  7) * X_STRIDE + row] = b.w;
        sX[(k0 +  8) * X_STRIDE + row] = d.x;
        sX[(k0 +  9) * X_STRIDE + row] = d.y;
        sX[(k0 + 10) * X_STRIDE + row] = d.z;
        sX[(k0 + 11) * X_STRIDE + row] = d.w;
        sX[(k0 + 12) * X_STRIDE + row] = e.x;
        sX[(k0 + 13) * X_STRIDE + row] = e.y;
        sX[(k0 + 14) * X_STRIDE + row] = e.z;
        sX[(k0 + 15) * X_STRIDE + row] = e.w;
    } else {
        // spline chunk: 4 features per row (2 KB)
        if (tid < 128) {
            const int row = tid;
            float4 a = *reinterpret_cast<const float4*>(
                X + (size_t)(rbase + row) * 256 + (c - 8) * 4);
            sX[0 * X_STRIDE + row] = a.x;
            sX[1 * X_STRIDE + row] = a.y;
            sX[2 * X_STRIDE + row] = a.z;
            sX[3 * X_STRIDE + row] = a.w;
        }
    }
}

static __device__ __forceinline__ void gen_a(
    int c, float* __restrict__ sA, const float* __restrict__ sX, int tid,
    const float* __restrict__ sg,
    const float (*__restrict__ siL)[10], const float (*__restrict__ siR)[10])
{
    if (c >= NCHUNK) return;
    const int r     = tid & 127;
    const int mf    = r >> 4;
    const int rhalf = (r >> 3) & 1;
    const int lnb   = (r & 7) * 4;
#pragma unroll
    for (int hh = 0; hh < 2; ++hh) {
        const int h = ((tid >> 7) << 1) | hh;   // 0..3 -> k group [h*8, h*8+8)
        if (c < 8) {
#pragma unroll
            for (int u = 0; u < 8; ++u) {
                float x = sX[(h * 8 + u) * X_STRIDE + r];
                float s = tf32_rn(__fdividef(x, 1.0f + __expf(-x)));
                sA[A_OFF(mf, h, rhalf + 2 * ((u >> 2) & 1), lnb + (u & 3))] = s;
            }
        } else {
            const float x = sX[h * X_STRIDE + r];
            float bs[11];
#pragma unroll
            for (int j = 0; j < 11; ++j)
                bs[j] = (x >= sg[j] && x < sg[j + 1]) ? 1.0f : 0.0f;
#pragma unroll
            for (int k = 1; k <= 3; ++k) {
#pragma unroll
                for (int j = 0; j < 10; ++j) {
                    if (j <= 10 - k)
                        bs[j] = (x - sg[j]) * siL[k - 1][j] * bs[j]
                              + (sg[j + k + 1] - x) * siR[k - 1][j] * bs[j + 1];
                }
            }
#pragma unroll
            for (int j = 0; j < 8; ++j)
                sA[A_OFF(mf, h, rhalf + 2 * ((j >> 2) & 1), lnb + (j & 3))]
                    = tf32_rn(bs[j]);
        }
    }
}

__global__ void __launch_bounds__(TPB, 2) kan_kernel(
    const float* __restrict__ X,    // [32768,256]
    const float* __restrict__ G,    // [12]
    float* __restrict__ OUT)        // [32768,256]
{
    extern __shared__ float sm[];
    float* sA  = sm;                      // 2 * A_WORDS
    float* sXs = sm + 2 * A_WORDS;        // 2 * X_WORDS
    __shared__ float s_g[12];
    __shared__ float s_iL[3][10];
    __shared__ float s_iR[3][10];

    const int tid  = threadIdx.x;
    const int wid  = tid >> 5;
    const int lane = tid & 31;

    if (tid < 12) s_g[tid] = G[tid];
    __syncthreads();
    if (tid < 30) {
        int k = tid / 10, j = tid % 10;   // k = order-1 (0..2)
        if (j <= 9 - k) {
            s_iL[k][j] = 1.0f / (s_g[j + k + 1] - s_g[j]);
            s_iR[k][j] = 1.0f / (s_g[j + k + 2] - s_g[j + 1]);
        }
    }
    __syncthreads();

    const int ntile  = blockIdx.x;        // 0/1: which 128-col half of N
    const int rbase  = blockIdx.y * 128;
    const int warp_m = wid & 1;           // 2 m-warps (64 rows each)
    const int warp_n = wid >> 1;          // 4 n-warps (32 cols each)
    const int nfg0   = ntile * 16 + warp_n * 4;   // wfrag group base
    const float2* __restrict__ wfrag = g_wfrag;

    float acc[4][4][4];
#pragma unroll
    for (int mf = 0; mf < 4; ++mf)
#pragma unroll
        for (int nf = 0; nf < 4; ++nf)
#pragma unroll
            for (int rr = 0; rr < 4; ++rr) acc[mf][nf][rr] = 0.0f;

    // prologue: stage X for chunks 0 and 1, generate A for chunk 0
    stage_x(0, sXs,           rbase, tid, X);
    stage_x(1, sXs + X_WORDS, rbase, tid, X);
    __syncthreads();
    gen_a(0, sA, sXs, tid, s_g, s_iL, s_iR);
    __syncthreads();

    for (int c = 0; c < NCHUNK; ++c) {
        // stage X for chunk c+2 (its buffer's last reader, gen_a(c), already done)
        stage_x(c + 2, sXs + (c & 1) * X_WORDS, rbase, tid, X);
        // generate A for chunk c+1 into buffer (c+1)&1
        gen_a(c + 1, sA + ((c + 1) & 1) * A_WORDS,
              sXs + ((c + 1) & 1) * X_WORDS, tid, s_g, s_iL, s_iR);

        const float* bufA = sA + (c & 1) * A_WORDS;
        const float2* wf = wfrag + (size_t)c * (32 * 4 * 32);

#pragma unroll
        for (int ks = 0; ks < 4; ++ks) {
            // B fragments: coalesced LDG.64 from L2-resident fragment scratch
            float2 bv[4];
#pragma unroll
            for (int nf = 0; nf < 4; ++nf)
                bv[nf] = wf[(((nfg0 + nf) * 4 + ks) << 5) + lane];

            uint32_t a[4][4];
#pragma unroll
            for (int mf = 0; mf < 4; ++mf) {
                const int base = A_OFF(warp_m * 4 + mf, ks, 0, lane);
#pragma unroll
                for (int rg = 0; rg < 4; ++rg)
                    a[mf][rg] = __float_as_uint(bufA[base + rg * 33]);
            }
#pragma unroll
            for (int nf = 0; nf < 4; ++nf) {
                const uint32_t b0 = __float_as_uint(bv[nf].x);
                const uint32_t b1 = __float_as_uint(bv[nf].y);
#pragma unroll
                for (int mf = 0; mf < 4; ++mf) {
                    asm volatile(
                        "mma.sync.aligned.m16n8k8.row.col.f32.tf32.tf32.f32 "
                        "{%0,%1,%2,%3}, {%4,%5,%6,%7}, {%8,%9}, {%0,%1,%2,%3};"
                        : "+f"(acc[mf][nf][0]), "+f"(acc[mf][nf][1]),
                          "+f"(acc[mf][nf][2]), "+f"(acc[mf][nf][3])
                        : "r"(a[mf][0]), "r"(a[mf][1]), "r"(a[mf][2]), "r"(a[mf][3]),
                          "r"(b0), "r"(b1));
                }
            }
        }
        __syncthreads();
    }

    // ---------------- epilogue: registers -> GMEM ----------------
    const int g = lane >> 2, t = lane & 3;
    const int cbase = ntile * 128 + warp_n * 32;
#pragma unroll
    for (int mf = 0; mf < 4; ++mf) {
#pragma unroll
        for (int nf = 0; nf < 4; ++nf) {
            const int row = rbase + warp_m * 64 + mf * 16 + g;
            const int col = cbase + nf * 8 + t * 2;
            float2 lo; lo.x = acc[mf][nf][0]; lo.y = acc[mf][nf][1];
            float2 hi; hi.x = acc[mf][nf][2]; hi.y = acc[mf][nf][3];
            *reinterpret_cast<float2*>(OUT + (size_t)row * 256 + col) = lo;
            *reinterpret_cast<float2*>(OUT + (size_t)(row + 8) * 256 + col) = hi;
        }
    }
}

extern "C" void kernel_launch(void* const* d_in, const int* in_sizes, int n_in,
                              void* d_out, int out_size) {
    const float* X  = (const float*)d_in[0];
    const float* BW = (const float*)d_in[1];
    const float* SW = (const float*)d_in[2];
    const float* SS = (const float*)d_in[3];
    const float* G  = (const float*)d_in[4];
    float* OUT = (float*)d_out;
    (void)in_sizes; (void)n_in; (void)out_size;

    wfrag_kernel<<<NCHUNK * 32 * 4 * 32 / 256, 256>>>(BW, SW, SS);

    cudaFuncSetAttribute(kan_kernel, cudaFuncAttributeMaxDynamicSharedMemorySize,
                         SMEM_BYTES);
    kan_kernel<<<dim3(2, 256), TPB, SMEM_BYTES>>>(X, G, OUT);
}

// round 13
// speedup vs baseline: 1.5370x; 1.5370x over previous
#include <cuda_runtime.h>
#include <cstdint>

// KANLinear fused as one tf32 mma.sync GEMM:
//   out[32768,256] = A[32768,2304] @ W[256,2304]^T
//   A = [ silu(x) | b_splines(x) flat ],  W = [ base_weight | spline_weight*scaler ]
// Round 13: M-split for dual residency. 512 CTAs, BM=64 x BN=256, TPB=256
// (8 warps all-N, warp tile 64x32), __launch_bounds__(256,2) -> 2 CTAs/SM.
// A generated once per row (no duplicate gen). W pre-fragmented in gmem
// (coalesced LDG.64, L2-resident). X staged through smem coalesced.

#define TPB 256
#define NCHUNK 72
// A layout: [mfrag 0..3][kstep 0..3][reg 0..3][lane 0..31], padded strides:
#define A_OFF(mf,ks,rg,ln) ((mf)*546 + (ks)*132 + (rg)*33 + (ln))
#define A_WORDS 2184          // 4*546
#define X_STRIDE 65           // k-major X stage: sX[k][row], padded row stride
#define X_WORDS (32 * X_STRIDE)
#define SMEM_BYTES ((2 * A_WORDS + 2 * X_WORDS) * 4)   // 34112

// W fragments: [chunk 0..71][nf_g 0..31][ks 0..3][lane 0..31] -> float2 (b0,b1)
__device__ float2 g_wfrag[NCHUNK * 32 * 4 * 32];

static __device__ __forceinline__ float tf32_rn(float f) {
    uint32_t u;
    asm("cvt.rna.tf32.f32 %0, %1;" : "=r"(u) : "f"(f));
    return __uint_as_float(u);
}

// ---------------- pre-kernel: build W fragments ----------------
static __device__ __forceinline__ float waug(
    int n, int K, const float* __restrict__ BW, const float* __restrict__ SW,
    const float* __restrict__ SS)
{
    if (K < 256) return tf32_rn(BW[(size_t)n * 256 + K]);
    int F = K - 256;
    int f = F >> 3, cf = F & 7;
    return tf32_rn(SW[((size_t)n * 256 + f) * 8 + cf] * SS[(size_t)n * 256 + f]);
}

__global__ void wfrag_kernel(const float* __restrict__ BW,
                             const float* __restrict__ SW,
                             const float* __restrict__ SS)
{
    int idx = blockIdx.x * 256 + threadIdx.x;          // 0 .. 294911
    int lane = idx & 31;
    int ks   = (idx >> 5) & 3;
    int nfg  = (idx >> 7) & 31;
    int c    = idx >> 12;
    int n = nfg * 8 + (lane >> 2);
    int t = lane & 3;
    int K0 = c * 32 + ks * 8 + t;
    float2 v;
    v.x = waug(n, K0,     BW, SW, SS);
    v.y = waug(n, K0 + 4, BW, SW, SS);
    g_wfrag[idx] = v;
}

// ---------------- main kernel helpers ----------------
static __device__ __forceinline__ void stage_x(
    int c, float* __restrict__ sX, int rbase, int tid, const float* __restrict__ X)
{
    if (c >= NCHUNK) return;
    if (c < 8) {
        // silu chunk: X[row][c*32 .. c*32+32), 64 rows; each line read once
        const int row = tid & 63, seg = tid >> 6;       // seg 0..3: 8 k each
        const float4* p = reinterpret_cast<const float4*>(
            X + (size_t)(rbase + row) * 256 + c * 32 + seg * 8);
        float4 a = p[0], b = p[1];
        const int k0 = seg * 8;
        sX[(k0 + 0) * X_STRIDE + row] = a.x;
        sX[(k0 + 1) * X_STRIDE + row] = a.y;
        sX[(k0 + 2) * X_STRIDE + row] = a.z;
        sX[(k0 + 3) * X_STRIDE + row] = a.w;
        sX[(k0 + 4) * X_STRIDE + row] = b.x;
        sX[(k0 + 5) * X_STRIDE + row] = b.y;
        sX[(k0 + 6) * X_STRIDE + row] = b.z;
        sX[(k0 + 7) * X_STRIDE + row] = b.w;
    } else {
        // spline chunk: 4 features per row (1 KB)
        if (tid < 64) {
            const int row = tid;
            float4 a = *reinterpret_cast<const float4*>(
                X + (size_t)(rbase + row) * 256 + (c - 8) * 4);
            sX[0 * X_STRIDE + row] = a.x;
            sX[1 * X_STRIDE + row] = a.y;
            sX[2 * X_STRIDE + row] = a.z;
            sX[3 * X_STRIDE + row] = a.w;
        }
    }
}

static __device__ __forceinline__ void gen_a(
    int c, float* __restrict__ sA, const float* __restrict__ sX, int tid,
    const float* __restrict__ sg,
    const float (*__restrict__ siL)[10], const float (*__restrict__ siR)[10])
{
    if (c >= NCHUNK) return;
    const int r     = tid & 63;
    const int h     = tid >> 6;          // 0..3 -> k group [h*8, h*8+8)
    const int mf    = r >> 4;
    const int rhalf = (r >> 3) & 1;
    const int lnb   = (r & 7) * 4;
    if (c < 8) {
#pragma unroll
        for (int u = 0; u < 8; ++u) {
            float x = sX[(h * 8 + u) * X_STRIDE + r];
            float s = tf32_rn(__fdividef(x, 1.0f + __expf(-x)));
            sA[A_OFF(mf, h, rhalf + 2 * ((u >> 2) & 1), lnb + (u & 3))] = s;
        }
    } else {
        const float x = sX[h * X_STRIDE + r];
        float bs[11];
#pragma unroll
        for (int j = 0; j < 11; ++j)
            bs[j] = (x >= sg[j] && x < sg[j + 1]) ? 1.0f : 0.0f;
#pragma unroll
        for (int k = 1; k <= 3; ++k) {
#pragma unroll
            for (int j = 0; j < 10; ++j) {
                if (j <= 10 - k)
                    bs[j] = (x - sg[j]) * siL[k - 1][j] * bs[j]
                          + (sg[j + k + 1] - x) * siR[k - 1][j] * bs[j + 1];
            }
        }
#pragma unroll
        for (int j = 0; j < 8; ++j)
            sA[A_OFF(mf, h, rhalf + 2 * ((j >> 2) & 1), lnb + (j & 3))] = tf32_rn(bs[j]);
    }
}

__global__ void __launch_bounds__(TPB, 2) kan_kernel(
    const float* __restrict__ X,    // [32768,256]
    const float* __restrict__ G,    // [12]
    float* __restrict__ OUT)        // [32768,256]
{
    extern __shared__ float sm[];
    float* sA  = sm;                      // 2 * A_WORDS
    float* sXs = sm + 2 * A_WORDS;        // 2 * X_WORDS
    __shared__ float s_g[12];
    __shared__ float s_iL[3][10];
    __shared__ float s_iR[3][10];

    const int tid  = threadIdx.x;
    const int wid  = tid >> 5;
    const int lane = tid & 31;

    if (tid < 12) s_g[tid] = G[tid];
    __syncthreads();
    if (tid < 30) {
        int k = tid / 10, j = tid % 10;   // k = order-1 (0..2)
        if (j <= 9 - k) {
            s_iL[k][j] = 1.0f / (s_g[j + k + 1] - s_g[j]);
            s_iR[k][j] = 1.0f / (s_g[j + k + 2] - s_g[j + 1]);
        }
    }
    __syncthreads();

    const int rbase  = blockIdx.x * 64;
    const int warp_n = wid;               // 8 n-warps (32 cols each)
    const int nfg0   = warp_n * 4;        // wfrag group base
    const float2* __restrict__ wfrag = g_wfrag;

    float acc[4][4][4];
#pragma unroll
    for (int mf = 0; mf < 4; ++mf)
#pragma unroll
        for (int nf = 0; nf < 4; ++nf)
#pragma unroll
            for (int rr = 0; rr < 4; ++rr) acc[mf][nf][rr] = 0.0f;

    // prologue: stage X for chunks 0 and 1, generate A for chunk 0
    stage_x(0, sXs,           rbase, tid, X);
    stage_x(1, sXs + X_WORDS, rbase, tid, X);
    __syncthreads();
    gen_a(0, sA, sXs, tid, s_g, s_iL, s_iR);
    __syncthreads();

    for (int c = 0; c < NCHUNK; ++c) {
        // stage X for chunk c+2 (its buffer's last reader, gen_a(c), already done)
        stage_x(c + 2, sXs + (c & 1) * X_WORDS, rbase, tid, X);
        // generate A for chunk c+1 into buffer (c+1)&1
        gen_a(c + 1, sA + ((c + 1) & 1) * A_WORDS,
              sXs + ((c + 1) & 1) * X_WORDS, tid, s_g, s_iL, s_iR);

        const float* bufA = sA + (c & 1) * A_WORDS;
        const float2* wf = wfrag + (size_t)c * (32 * 4 * 32);

#pragma unroll
        for (int ks = 0; ks < 4; ++ks) {
            // B fragments: coalesced LDG.64 from L2-resident fragment scratch
            float2 bv[4];
#pragma unroll
            for (int nf = 0; nf < 4; ++nf)
                bv[nf] = wf[(((nfg0 + nf) * 4 + ks) << 5) + lane];

            uint32_t a[4][4];
#pragma unroll
            for (int mf = 0; mf < 4; ++mf) {
                const int base = A_OFF(mf, ks, 0, lane);
#pragma unroll
                for (int rg = 0; rg < 4; ++rg)
                    a[mf][rg] = __float_as_uint(bufA[base + rg * 33]);
            }
#pragma unroll
            for (int nf = 0; nf < 4; ++nf) {
                const uint32_t b0 = __float_as_uint(bv[nf].x);
                const uint32_t b1 = __float_as_uint(bv[nf].y);
#pragma unroll
                for (int mf = 0; mf < 4; ++mf) {
                    asm volatile(
                        "mma.sync.aligned.m16n8k8.row.col.f32.tf32.tf32.f32 "
                        "{%0,%1,%2,%3}, {%4,%5,%6,%7}, {%8,%9}, {%0,%1,%2,%3};"
                        : "+f"(acc[mf][nf][0]), "+f"(acc[mf][nf][1]),
                          "+f"(acc[mf][nf][2]), "+f"(acc[mf][nf][3])
                        : "r"(a[mf][0]), "r"(a[mf][1]), "r"(a[mf][2]), "r"(a[mf][3]),
                          "r"(b0), "r"(b1));
                }
            }
        }
        __syncthreads();
    }

    // ---------------- epilogue: registers -> GMEM ----------------
    const int g = lane >> 2, t = lane & 3;
    const int cbase = warp_n * 32;
#pragma unroll
    for (int mf = 0; mf < 4; ++mf) {
#pragma unroll
        for (int nf = 0; nf < 4; ++nf) {
            const int row = rbase + mf * 16 + g;
            const int col = cbase + nf * 8 + t * 2;
            float2 lo; lo.x = acc[mf][nf][0]; lo.y = acc[mf][nf][1];
            float2 hi; hi.x = acc[mf][nf][2]; hi.y = acc[mf][nf][3];
            *reinterpret_cast<float2*>(OUT + (size_t)row * 256 + col) = lo;
            *reinterpret_cast<float2*>(OUT + (size_t)(row + 8) * 256 + col) = hi;
        }
    }
}

extern "C" void kernel_launch(void* const* d_in, const int* in_sizes, int n_in,
                              void* d_out, int out_size) {
    const float* X  = (const float*)d_in[0];
    const float* BW = (const float*)d_in[1];
    const float* SW = (const float*)d_in[2];
    const float* SS = (const float*)d_in[3];
    const float* G  = (const float*)d_in[4];
    float* OUT = (float*)d_out;
    (void)in_sizes; (void)n_in; (void)out_size;

    wfrag_kernel<<<NCHUNK * 32 * 4 * 32 / 256, 256>>>(BW, SW, SS);

    cudaFuncSetAttribute(kan_kernel, cudaFuncAttributeMaxDynamicSharedMemorySize,
                         SMEM_BYTES);
    kan_kernel<<<512, TPB, SMEM_BYTES>>>(X, G, OUT);
}